// round 6
// baseline (speedup 1.0000x reference)
#include <cuda_runtime.h>
#include <cuda_fp16.h>
#include <cuda_bf16.h>

#define NN 4
#define NQ 256
#define NV 512
#define NE 256

// Scratch (allocation-free requirement)
__device__ float g_expl[NN * NQ * NV];       // exp(logit/t)  (2 MB)
__device__ float g_denp[NN * NQ * 8];        // per-64v denominator partials
__device__ float g_pvp[4][NN * NQ * NE];     // split-4 partials of exp@memory (4 MB)
__device__ float g_heads[NN * NQ * NE];      // normalized, leaky heads (1 MB)

// ---------------------------------------------------------------------------
// helpers
// ---------------------------------------------------------------------------
__device__ __forceinline__ uint4 pack8(const float4 a, const float4 b) {
    __half2 h0 = __floats2half2_rn(a.x, a.y);
    __half2 h1 = __floats2half2_rn(a.z, a.w);
    __half2 h2 = __floats2half2_rn(b.x, b.y);
    __half2 h3 = __floats2half2_rn(b.z, b.w);
    uint4 r;
    r.x = *reinterpret_cast<unsigned*>(&h0);
    r.y = *reinterpret_cast<unsigned*>(&h1);
    r.z = *reinterpret_cast<unsigned*>(&h2);
    r.w = *reinterpret_cast<unsigned*>(&h3);
    return r;
}

__device__ __forceinline__ __half2 u2h(unsigned u) {
    return *reinterpret_cast<__half2*>(&u);
}

// tanh of (q+c) in f16x2, times w (f16x2)
__device__ __forceinline__ __half2 wtanh(unsigned cv, unsigned qv, unsigned wv) {
    __half2 s = __hadd2(u2h(qv), u2h(cv));
    unsigned su = *reinterpret_cast<unsigned*>(&s);
    unsigned tu;
    asm("tanh.approx.f16x2 %0, %1;" : "=r"(tu) : "r"(su));
    return __hmul2(u2h(tu), u2h(wv));
}

// packed f32x2 FMA
__device__ __forceinline__ unsigned long long splat2(float x) {
    unsigned long long r;
    asm("mov.b64 %0, {%1, %1};" : "=l"(r) : "r"(__float_as_uint(x)));
    return r;
}
__device__ __forceinline__ void ffma2(unsigned long long& d,
                                      unsigned long long a, unsigned long long b) {
    asm("fma.rn.f32x2 %0, %1, %2, %0;" : "+l"(d) : "l"(a), "l"(b));
}

// ---------------------------------------------------------------------------
// K1: e[n,q,v] = exp( (sum_e w*tanh(q+c) + b) / t ), plus per-64v denom
// partials. Warp = q-row, lane = v. f16x2 tanh octet pipeline.
// ---------------------------------------------------------------------------
__global__ void __launch_bounds__(256) k_logits(
    const float* __restrict__ q, const float* __restrict__ c,
    const float* __restrict__ wl, const float* __restrict__ bl_p,
    const float* __restrict__ temp_p)
{
    __shared__ uint4 ct[32][33];    // 16.9 KB, [e-octet][v]
    __shared__ uint4 qs[8][32];     // 4 KB
    __shared__ uint4 ws[32];        // 512 B

    const int n = blockIdx.z;
    const int qbase = blockIdx.x * 8;
    const int tid = threadIdx.x;
    const int wq = tid >> 5, lane = tid & 31;

    {   // one q-octet per thread
        int r = tid >> 5, g = tid & 31;
        const float4* src =
            (const float4*)&q[((size_t)n * NQ + qbase + r) * NE + g * 8];
        qs[r][g] = pack8(src[0], src[1]);
    }
    if (tid < 32) {
        const float4* src = (const float4*)&wl[tid * 8];
        ws[tid] = pack8(src[0], src[1]);
    }
    const float bl = __ldg(bl_p);
    const float invt = 1.0f / __ldg(temp_p);

    float dsum = 0.f;
    #pragma unroll
    for (int t = 0; t < 2; ++t) {
        __syncthreads();
        const int vbase = blockIdx.y * 64 + t * 32;
        for (int i = tid; i < 1024; i += 256) {   // 32 v x 32 octets
            int v = i >> 5, g = i & 31;
            const float4* src =
                (const float4*)&c[((size_t)n * NV + vbase + v) * NE + g * 8];
            ct[g][v] = pack8(src[0], src[1]);
        }
        __syncthreads();

        float a0 = 0.f, a1 = 0.f;
        #pragma unroll 8
        for (int g = 0; g < 32; ++g) {
            uint4 cb = ct[g][lane];
            uint4 qb = qs[wq][g];
            uint4 wb = ws[g];
            __half2 p0 = wtanh(cb.x, qb.x, wb.x);
            __half2 p1 = wtanh(cb.y, qb.y, wb.y);
            __half2 p2 = wtanh(cb.z, qb.z, wb.z);
            __half2 p3 = wtanh(cb.w, qb.w, wb.w);
            __half2 ps = __hadd2(__hadd2(p0, p1), __hadd2(p2, p3));
            float2 f = __half22float2(ps);
            a0 += f.x;
            a1 += f.y;
        }
        float e = __expf((a0 + a1 + bl) * invt);
        dsum += e;
        g_expl[((size_t)n * NQ + qbase + wq) * NV + vbase + lane] = e;
    }

    // warp-reduce dsum over 32 lanes (covers this block's 64 v's for row wq)
    #pragma unroll
    for (int o = 16; o; o >>= 1) dsum += __shfl_xor_sync(0xffffffffu, dsum, o);
    if (lane == 0)
        g_denp[((size_t)n * NQ + qbase + wq) * 8 + blockIdx.y] = dsum;
}

// ---------------------------------------------------------------------------
// K2: split-4(BK=128) of e @ memory. Plain A copy (exp precomputed),
// register-prefetch pipelined 4x4 micro-tile, stride-72 smem (frag reads
// 16B-aligned: 288k+16t; staging stores conflict-free / 2-way).
// ---------------------------------------------------------------------------
__global__ void __launch_bounds__(256) k_pv(const float* __restrict__ Mm)
{
    const int n = blockIdx.z >> 2, s = blockIdx.z & 3;
    const int m0 = blockIdx.y * 64, n0 = blockIdx.x * 64;
    const float* A = g_expl + (size_t)n * NQ * NV;
    const float* B = Mm + (size_t)n * NV * NE;

    __shared__ float As[32][72];
    __shared__ float Bs[32][72];

    const int tid = threadIdx.x;
    const int tx = tid & 15, ty = tid >> 4;
    const int ar = tid >> 2, ac = (tid & 3) * 8;
    const int bkr = tid >> 3, bc = (tid & 7) * 8;

    unsigned long long acc[4][2] = {};

    #pragma unroll
    for (int it = 0; it < 4; ++it) {
        const int k0 = s * 128 + it * 32;
        float4 a0 = *(const float4*)&A[(size_t)(m0 + ar) * NV + k0 + ac];
        float4 a1 = *(const float4*)&A[(size_t)(m0 + ar) * NV + k0 + ac + 4];
        As[ac + 0][ar] = a0.x; As[ac + 1][ar] = a0.y;
        As[ac + 2][ar] = a0.z; As[ac + 3][ar] = a0.w;
        As[ac + 4][ar] = a1.x; As[ac + 5][ar] = a1.y;
        As[ac + 6][ar] = a1.z; As[ac + 7][ar] = a1.w;
        *(float4*)&Bs[bkr][bc] =
            *(const float4*)&B[(size_t)(k0 + bkr) * NE + n0 + bc];
        *(float4*)&Bs[bkr][bc + 4] =
            *(const float4*)&B[(size_t)(k0 + bkr) * NE + n0 + bc + 4];
        __syncthreads();

        float4 a_c = *(const float4*)&As[0][ty * 4];
        ulonglong2 b_c = *(const ulonglong2*)&Bs[0][tx * 4];
        #pragma unroll
        for (int k = 0; k < 32; ++k) {
            float4 a_n;
            ulonglong2 b_n;
            if (k < 31) {
                a_n = *(const float4*)&As[k + 1][ty * 4];
                b_n = *(const ulonglong2*)&Bs[k + 1][tx * 4];
            }
            ffma2(acc[0][0], splat2(a_c.x), b_c.x); ffma2(acc[0][1], splat2(a_c.x), b_c.y);
            ffma2(acc[1][0], splat2(a_c.y), b_c.x); ffma2(acc[1][1], splat2(a_c.y), b_c.y);
            ffma2(acc[2][0], splat2(a_c.z), b_c.x); ffma2(acc[2][1], splat2(a_c.z), b_c.y);
            ffma2(acc[3][0], splat2(a_c.w), b_c.x); ffma2(acc[3][1], splat2(a_c.w), b_c.y);
            if (k < 31) { a_c = a_n; b_c = b_n; }
        }
        __syncthreads();
    }

    float* P = g_pvp[s] + (size_t)n * NQ * NE;
    #pragma unroll
    for (int i = 0; i < 4; ++i) {
        float2 lo = *reinterpret_cast<float2*>(&acc[i][0]);
        float2 hi = *reinterpret_cast<float2*>(&acc[i][1]);
        *(float4*)&P[(size_t)(m0 + ty * 4 + i) * NE + n0 + tx * 4] =
            make_float4(lo.x, lo.y, hi.x, hi.y);
    }
}

// ---------------------------------------------------------------------------
// K3: heads = leaky( (sum_s pvp) / (sum_vb denp) )
// ---------------------------------------------------------------------------
__global__ void __launch_bounds__(256) k_merge()
{
    const int i = blockIdx.x * 256 + threadIdx.x;   // float4 idx, 65536 total
    const int row = i >> 6;

    float dt = 0.f;
    #pragma unroll
    for (int vb = 0; vb < 8; ++vb) dt += g_denp[(size_t)row * 8 + vb];
    const float inv = 1.0f / dt;

    float4 s = make_float4(0.f, 0.f, 0.f, 0.f);
    #pragma unroll
    for (int sp = 0; sp < 4; ++sp) {
        float4 p = *(const float4*)&g_pvp[sp][(size_t)i * 4];
        s.x += p.x; s.y += p.y; s.z += p.z; s.w += p.w;
    }
    float h0 = s.x * inv, h1 = s.y * inv, h2 = s.z * inv, h3 = s.w * inv;
    float4 r;
    r.x = (h0 > 0.f) ? h0 : 0.01f * h0;
    r.y = (h1 > 0.f) ? h1 : 0.01f * h1;
    r.z = (h2 > 0.f) ? h2 : 0.01f * h2;
    r.w = (h3 > 0.f) ? h3 : 0.01f * h3;
    *(float4*)&g_heads[(size_t)i * 4] = r;
}

// ---------------------------------------------------------------------------
// K4: out = heads @ Wr^T + bias. 32x32 tiles -> 256 blocks (2048 warps),
// 2x2 micro-tile, register-prefetch pipeline. stride-34 smem: frag float2
// reads at 136k+8t are 8B-aligned and conflict-free (128B rows).
// ---------------------------------------------------------------------------
__global__ void __launch_bounds__(256) k_out(
    const float* __restrict__ Wr, const float* __restrict__ br_p,
    float* __restrict__ out)
{
    const int n = blockIdx.z;
    const int m0 = blockIdx.y * 32, n0 = blockIdx.x * 32;
    const float* A = g_heads + (size_t)n * NQ * NE;

    __shared__ float As[32][34];
    __shared__ float Bs[32][34];

    const int tid = threadIdx.x;
    const int tx = tid & 15, ty = tid >> 4;        // 16 x 16 -> 2n x 2m
    const int sr = tid >> 3, sc = (tid & 7) * 4;   // staging: 32 rows x 8 q-cols

    unsigned long long acc[2] = {};                // [m-row][2 n packed]

    for (int k0 = 0; k0 < NE; k0 += 32) {
        // A tile: heads[m0+sr][k0+sc..+3] -> As[k][m] transposed
        float4 av = *(const float4*)&A[(size_t)(m0 + sr) * NE + k0 + sc];
        As[sc + 0][sr] = av.x; As[sc + 1][sr] = av.y;
        As[sc + 2][sr] = av.z; As[sc + 3][sr] = av.w;
        // B tile: Wr[n0+sr][k0+sc..+3] -> Bs[k][j] transposed
        float4 bv = *(const float4*)&Wr[(size_t)(n0 + sr) * NE + k0 + sc];
        Bs[sc + 0][sr] = bv.x; Bs[sc + 1][sr] = bv.y;
        Bs[sc + 2][sr] = bv.z; Bs[sc + 3][sr] = bv.w;
        __syncthreads();

        float2 a_c = *(const float2*)&As[0][ty * 2];
        unsigned long long b_c = *(const unsigned long long*)&Bs[0][tx * 2];
        #pragma unroll
        for (int k = 0; k < 32; ++k) {
            float2 a_n;
            unsigned long long b_n;
            if (k < 31) {
                a_n = *(const float2*)&As[k + 1][ty * 2];
                b_n = *(const unsigned long long*)&Bs[k + 1][tx * 2];
            }
            ffma2(acc[0], splat2(a_c.x), b_c);
            ffma2(acc[1], splat2(a_c.y), b_c);
            if (k < 31) { a_c = a_n; b_c = b_n; }
        }
        __syncthreads();
    }

    float2 b2 = *(const float2*)&br_p[n0 + tx * 2];
    #pragma unroll
    for (int i = 0; i < 2; ++i) {
        float2 v = *reinterpret_cast<float2*>(&acc[i]);
        float2 r = make_float2(v.x + b2.x, v.y + b2.y);
        *(float2*)&out[((size_t)n * NQ + m0 + ty * 2 + i) * NE + n0 + tx * 2] = r;
    }
}

// ---------------------------------------------------------------------------
extern "C" void kernel_launch(void* const* d_in, const int* in_sizes, int n_in,
                              void* d_out, int out_size)
{
    const float* query   = (const float*)d_in[0];
    const float* context = (const float*)d_in[1];
    const float* memory  = (const float*)d_in[2];
    const float* w_logit = (const float*)d_in[3];
    const float* b_logit = (const float*)d_in[4];
    const float* temp    = (const float*)d_in[5];
    const float* w_red   = (const float*)d_in[6];
    const float* b_red   = (const float*)d_in[7];
    float* out = (float*)d_out;

    dim3 g1(NQ / 8, NV / 64, NN);        // 32 x 8 x 4 = 1024 blocks
    k_logits<<<g1, 256>>>(query, context, w_logit, b_logit, temp);

    dim3 g2(NE / 64, NQ / 64, NN * 4);   // 4 x 4 x 16 = 256 blocks
    k_pv<<<g2, 256>>>(memory);

    k_merge<<<256, 256>>>();             // 65536 float4

    dim3 g4(NE / 32, NQ / 32, NN);       // 8 x 8 x 4 = 256 blocks
    k_out<<<g4, 256>>>(w_red, b_red, out);
}

// round 7
// speedup vs baseline: 1.6149x; 1.6149x over previous
#include <cuda_runtime.h>
#include <cuda_fp16.h>
#include <cuda_bf16.h>

#define NN 4
#define NQ 256
#define NV 512
#define NE 256

// Scratch (allocation-free requirement)
__device__ float g_expl[NN * NQ * NV];       // exp(logit/t)  (2 MB)
__device__ float g_denp[NN * NQ * 8];        // per-64v denominator partials
__device__ float g_pvp[8][NN * NQ * NE];     // split-8 partials of exp@memory (8 MB)
__device__ float g_heads[NN * NQ * NE];      // normalized, leaky heads (1 MB)
__device__ float g_rdp[4][NN * NQ * NE];     // split-4 partials of heads@Wr^T (4 MB)

// ---------------------------------------------------------------------------
// helpers
// ---------------------------------------------------------------------------
__device__ __forceinline__ uint4 pack8(const float4 a, const float4 b) {
    __half2 h0 = __floats2half2_rn(a.x, a.y);
    __half2 h1 = __floats2half2_rn(a.z, a.w);
    __half2 h2 = __floats2half2_rn(b.x, b.y);
    __half2 h3 = __floats2half2_rn(b.z, b.w);
    uint4 r;
    r.x = *reinterpret_cast<unsigned*>(&h0);
    r.y = *reinterpret_cast<unsigned*>(&h1);
    r.z = *reinterpret_cast<unsigned*>(&h2);
    r.w = *reinterpret_cast<unsigned*>(&h3);
    return r;
}

__device__ __forceinline__ __half2 u2h(unsigned u) {
    return *reinterpret_cast<__half2*>(&u);
}

// tanh of (q+c) in f16x2, times w (f16x2)
__device__ __forceinline__ __half2 wtanh(unsigned cv, unsigned qv, unsigned wv) {
    __half2 s = __hadd2(u2h(qv), u2h(cv));
    unsigned su = *reinterpret_cast<unsigned*>(&s);
    unsigned tu;
    asm("tanh.approx.f16x2 %0, %1;" : "=r"(tu) : "r"(su));
    return __hmul2(u2h(tu), u2h(wv));
}

// ---------------------------------------------------------------------------
// K1: e[n,q,v] = exp( (sum_e w*tanh(q+c) + b) / t ), plus per-64v denom
// partials. Warp = q-row, lane = v. f16x2 tanh octet pipeline.
// ct row stride 33 uint4 (== 4 mod 32 words): conflict-free LDS.128 & STS.128.
// ---------------------------------------------------------------------------
__global__ void __launch_bounds__(256) k_logits(
    const float* __restrict__ q, const float* __restrict__ c,
    const float* __restrict__ wl, const float* __restrict__ bl_p,
    const float* __restrict__ temp_p)
{
    __shared__ uint4 ct[32][33];    // 16.9 KB, [e-octet][v]
    __shared__ uint4 qs[8][32];     // 4 KB
    __shared__ uint4 ws[32];        // 512 B

    const int n = blockIdx.z;
    const int qbase = blockIdx.x * 8;
    const int tid = threadIdx.x;
    const int wq = tid >> 5, lane = tid & 31;

    {   // one q-octet per thread
        int r = tid >> 5, g = tid & 31;
        const float4* src =
            (const float4*)&q[((size_t)n * NQ + qbase + r) * NE + g * 8];
        qs[r][g] = pack8(src[0], src[1]);
    }
    if (tid < 32) {
        const float4* src = (const float4*)&wl[tid * 8];
        ws[tid] = pack8(src[0], src[1]);
    }
    const float bl = __ldg(bl_p);
    const float invt = 1.0f / __ldg(temp_p);

    float dsum = 0.f;
    #pragma unroll
    for (int t = 0; t < 2; ++t) {
        __syncthreads();
        const int vbase = blockIdx.y * 64 + t * 32;
        for (int i = tid; i < 1024; i += 256) {   // 32 v x 32 octets
            int v = i >> 5, g = i & 31;
            const float4* src =
                (const float4*)&c[((size_t)n * NV + vbase + v) * NE + g * 8];
            ct[g][v] = pack8(src[0], src[1]);
        }
        __syncthreads();

        float a0 = 0.f, a1 = 0.f;
        #pragma unroll 8
        for (int g = 0; g < 32; ++g) {
            uint4 cb = ct[g][lane];
            uint4 qb = qs[wq][g];
            uint4 wb = ws[g];
            __half2 p0 = wtanh(cb.x, qb.x, wb.x);
            __half2 p1 = wtanh(cb.y, qb.y, wb.y);
            __half2 p2 = wtanh(cb.z, qb.z, wb.z);
            __half2 p3 = wtanh(cb.w, qb.w, wb.w);
            __half2 ps = __hadd2(__hadd2(p0, p1), __hadd2(p2, p3));
            float2 f = __half22float2(ps);
            a0 += f.x;
            a1 += f.y;
        }
        float e = __expf((a0 + a1 + bl) * invt);
        dsum += e;
        g_expl[((size_t)n * NQ + qbase + wq) * NV + vbase + lane] = e;
    }

    // warp-reduce dsum over 32 lanes (this block's 64 v's for row wq)
    #pragma unroll
    for (int o = 16; o; o >>= 1) dsum += __shfl_xor_sync(0xffffffffu, dsum, o);
    if (lane == 0)
        g_denp[((size_t)n * NQ + qbase + wq) * 8 + blockIdx.y] = dsum;
}

// ---------------------------------------------------------------------------
// K2: split-8(K-slice 64) of e @ memory. Plain copy A-staging, BK=16,
// 4x4 micro-tile, plain fmaf (r2-proven loop shape).
// ---------------------------------------------------------------------------
__global__ void __launch_bounds__(256) k_pv(const float* __restrict__ Mm)
{
    const int n = blockIdx.z >> 3, s = blockIdx.z & 7;
    const int m0 = blockIdx.y * 64, n0 = blockIdx.x * 64;
    const float* A = g_expl + (size_t)n * NQ * NV;
    const float* B = Mm + (size_t)n * NV * NE;

    __shared__ float As[16][68];
    __shared__ float Bs[16][68];

    const int tid = threadIdx.x;
    const int tx = tid & 15, ty = tid >> 4;
    const int ar = tid >> 2, ac = (tid & 3) * 4;  // A: 64 rows x 16 k
    const int br = tid >> 4, bc = (tid & 15) * 4; // B: 16 rows x 64 n

    float acc[4][4] = {};

    for (int k0 = s * 64; k0 < s * 64 + 64; k0 += 16) {
        float4 av = *(const float4*)&A[(size_t)(m0 + ar) * NV + k0 + ac];
        As[ac][ar]     = av.x; As[ac + 1][ar] = av.y;
        As[ac + 2][ar] = av.z; As[ac + 3][ar] = av.w;
        *(float4*)&Bs[br][bc] =
            *(const float4*)&B[(size_t)(k0 + br) * NE + n0 + bc];
        __syncthreads();
        #pragma unroll
        for (int k = 0; k < 16; ++k) {
            float a[4], b[4];
            *(float4*)a = *(const float4*)&As[k][ty * 4];
            *(float4*)b = *(const float4*)&Bs[k][tx * 4];
            #pragma unroll
            for (int i = 0; i < 4; ++i)
                #pragma unroll
                for (int j = 0; j < 4; ++j)
                    acc[i][j] += a[i] * b[j];
        }
        __syncthreads();
    }

    float* P = g_pvp[s] + (size_t)n * NQ * NE;
    #pragma unroll
    for (int i = 0; i < 4; ++i)
        *(float4*)&P[(size_t)(m0 + ty * 4 + i) * NE + n0 + tx * 4] =
            make_float4(acc[i][0], acc[i][1], acc[i][2], acc[i][3]);
}

// ---------------------------------------------------------------------------
// K3: heads = leaky( (sum_s pvp) / (sum_vb denp) )
// ---------------------------------------------------------------------------
__global__ void __launch_bounds__(256) k_merge()
{
    const int i = blockIdx.x * 256 + threadIdx.x;   // float4 idx, 65536 total
    const int row = i >> 6;

    float dt = 0.f;
    #pragma unroll
    for (int vb = 0; vb < 8; ++vb) dt += g_denp[(size_t)row * 8 + vb];
    const float inv = 1.0f / dt;

    float4 s = make_float4(0.f, 0.f, 0.f, 0.f);
    #pragma unroll
    for (int sp = 0; sp < 8; ++sp) {
        float4 p = *(const float4*)&g_pvp[sp][(size_t)i * 4];
        s.x += p.x; s.y += p.y; s.z += p.z; s.w += p.w;
    }
    float h0 = s.x * inv, h1 = s.y * inv, h2 = s.z * inv, h3 = s.w * inv;
    float4 r;
    r.x = (h0 > 0.f) ? h0 : 0.01f * h0;
    r.y = (h1 > 0.f) ? h1 : 0.01f * h1;
    r.z = (h2 > 0.f) ? h2 : 0.01f * h2;
    r.w = (h3 > 0.f) ? h3 : 0.01f * h3;
    *(float4*)&g_heads[(size_t)i * 4] = r;
}

// ---------------------------------------------------------------------------
// K4: split-4(K-slice 64) of heads @ Wr^T. 64x64 tiles, BK=16, 4x4 micro,
// plain fmaf, B transposed during staging. Writes partials.
// ---------------------------------------------------------------------------
__global__ void __launch_bounds__(256) k_out(const float* __restrict__ Wr)
{
    const int n = blockIdx.z >> 2, s = blockIdx.z & 3;
    const int m0 = blockIdx.y * 64, n0 = blockIdx.x * 64;
    const float* A = g_heads + (size_t)n * NQ * NE;

    __shared__ float As[16][68];
    __shared__ float Bs[16][68];

    const int tid = threadIdx.x;
    const int tx = tid & 15, ty = tid >> 4;
    const int ar = tid >> 2, ac = (tid & 3) * 4;

    float acc[4][4] = {};

    for (int k0 = s * 64; k0 < s * 64 + 64; k0 += 16) {
        float4 av = *(const float4*)&A[(size_t)(m0 + ar) * NE + k0 + ac];
        As[ac][ar]     = av.x; As[ac + 1][ar] = av.y;
        As[ac + 2][ar] = av.z; As[ac + 3][ar] = av.w;
        // Bs[k][j] = Wr[(n0+j)*NE + k0+k]  (transpose during staging)
        float4 bv = *(const float4*)&Wr[(size_t)(n0 + ar) * NE + k0 + ac];
        Bs[ac][ar]     = bv.x; Bs[ac + 1][ar] = bv.y;
        Bs[ac + 2][ar] = bv.z; Bs[ac + 3][ar] = bv.w;
        __syncthreads();
        #pragma unroll
        for (int k = 0; k < 16; ++k) {
            float a[4], b[4];
            *(float4*)a = *(const float4*)&As[k][ty * 4];
            *(float4*)b = *(const float4*)&Bs[k][tx * 4];
            #pragma unroll
            for (int i = 0; i < 4; ++i)
                #pragma unroll
                for (int j = 0; j < 4; ++j)
                    acc[i][j] += a[i] * b[j];
        }
        __syncthreads();
    }

    float* R = g_rdp[s] + (size_t)n * NQ * NE;
    #pragma unroll
    for (int i = 0; i < 4; ++i)
        *(float4*)&R[(size_t)(m0 + ty * 4 + i) * NE + n0 + tx * 4] =
            make_float4(acc[i][0], acc[i][1], acc[i][2], acc[i][3]);
}

// ---------------------------------------------------------------------------
// K5: out = sum of 4 reduce-partials + bias
// ---------------------------------------------------------------------------
__global__ void __launch_bounds__(256) k_final(
    const float* __restrict__ br_p, float* __restrict__ out)
{
    const int i = blockIdx.x * 256 + threadIdx.x;   // float4 idx, 65536 total
    const int col4 = i & 63;
    float4 r = *(const float4*)&br_p[col4 * 4];
    #pragma unroll
    for (int sp = 0; sp < 4; ++sp) {
        float4 p = *(const float4*)&g_rdp[sp][(size_t)i * 4];
        r.x += p.x; r.y += p.y; r.z += p.z; r.w += p.w;
    }
    *(float4*)&out[(size_t)i * 4] = r;
}

// ---------------------------------------------------------------------------
extern "C" void kernel_launch(void* const* d_in, const int* in_sizes, int n_in,
                              void* d_out, int out_size)
{
    const float* query   = (const float*)d_in[0];
    const float* context = (const float*)d_in[1];
    const float* memory  = (const float*)d_in[2];
    const float* w_logit = (const float*)d_in[3];
    const float* b_logit = (const float*)d_in[4];
    const float* temp    = (const float*)d_in[5];
    const float* w_red   = (const float*)d_in[6];
    const float* b_red   = (const float*)d_in[7];
    float* out = (float*)d_out;

    dim3 g1(NQ / 8, NV / 64, NN);        // 32 x 8 x 4 = 1024 blocks
    k_logits<<<g1, 256>>>(query, context, w_logit, b_logit, temp);

    dim3 g2(NE / 64, NQ / 64, NN * 8);   // 4 x 4 x 32 = 512 blocks
    k_pv<<<g2, 256>>>(memory);

    k_merge<<<256, 256>>>();             // 65536 float4

    dim3 g4(NE / 64, NQ / 64, NN * 4);   // 4 x 4 x 16 = 256 blocks
    k_out<<<g4, 256>>>(w_red);

    k_final<<<256, 256>>>(b_red, out);
}